// round 11
// baseline (speedup 1.0000x reference)
#include <cuda_runtime.h>
#include <cuda_fp16.h>
#include <math.h>
#include <stdint.h>

#define BB   32
#define NWAY 16
#define LQ   64
#define LD   256
#define DD   128
#define NEGV (-9999.0f)

typedef unsigned long long u64;

__device__ float g_scores[BB * NWAY];
__device__ int   g_cnt;                 // zero-init; reset by last CTA each launch

// ---------------- smem layout (dynamic) ----------------
// Tiles: 256B rows (16 x 16B units), unit swizzle: u' = u ^ (row & 7)
#define S_PART  0                       // 8*64 floats = 2048 (per-warp max strips)
#define S_WS    2048                    // 2 floats
#define S_QHI   4096                    // 64 x 256B  = 16384
#define S_QLO   20480
#define S_DH    36864                   // 128 x 256B = 32768 (warp-exclusive strips)
#define S_TOTAL 69632

__device__ __forceinline__ uint32_t smem_u32(const void* p) {
    uint32_t a;
    asm("{ .reg .u64 t; cvta.to.shared.u64 t, %1; cvt.u32.u64 %0, t; }" : "=r"(a) : "l"(p));
    return a;
}

__device__ __forceinline__ void ldsm4(uint32_t* r, uint32_t addr) {
    asm volatile("ldmatrix.sync.aligned.m8n8.x4.shared.b16 {%0,%1,%2,%3}, [%4];"
                 : "=r"(r[0]), "=r"(r[1]), "=r"(r[2]), "=r"(r[3]) : "r"(addr));
}

__device__ __forceinline__ void mma_f16(float* c, const uint32_t* a, uint32_t b0, uint32_t b1) {
    asm volatile(
        "mma.sync.aligned.m16n8k16.row.col.f32.f16.f16.f32 "
        "{%0,%1,%2,%3}, {%4,%5,%6,%7}, {%8,%9}, {%0,%1,%2,%3};"
        : "+f"(c[0]), "+f"(c[1]), "+f"(c[2]), "+f"(c[3])
        : "r"(a[0]), "r"(a[1]), "r"(a[2]), "r"(a[3]), "r"(b0), "r"(b1));
}

// float4 -> 4 fp16 (rounded), packed in u64
__device__ __forceinline__ u64 cvt4h(float4 v) {
    __half2 a = __floats2half2_rn(v.x, v.y);
    __half2 b = __floats2half2_rn(v.z, v.w);
    return (u64)*(uint32_t*)&a | ((u64)*(uint32_t*)&b << 32);
}

// float4 -> fp16 hi/lo split (q operand: near-exact 2-term)
__device__ __forceinline__ void split4h(float4 v, u64& hi, u64& lo) {
    __half2 a = __floats2half2_rn(v.x, v.y);
    __half2 b = __floats2half2_rn(v.z, v.w);
    float2 fa = __half22float2(a), fb = __half22float2(b);
    __half2 la = __floats2half2_rn(v.x - fa.x, v.y - fa.y);
    __half2 lb = __floats2half2_rn(v.z - fb.x, v.w - fb.y);
    hi = (u64)*(uint32_t*)&a  | ((u64)*(uint32_t*)&b  << 32);
    lo = (u64)*(uint32_t*)&la | ((u64)*(uint32_t*)&lb << 32);
}

// ---------------------------------------------------------------------------
// One CTA per (b,n). 256 threads, 3 CTAs/SM (84-reg cap).
// ---------------------------------------------------------------------------
__global__ void __launch_bounds__(256, 3) colbert_mma(
    const float* __restrict__ qreps, const float* __restrict__ dreps,
    const int* __restrict__ dmask, const float* __restrict__ labels,
    float* __restrict__ out)
{
    extern __shared__ char smem[];
    const uint32_t sbase = smem_u32(smem);
    float* part = (float*)(smem + S_PART);
    float* ws   = (float*)(smem + S_WS);

    const int bn   = blockIdx.x;       // b*16 + n
    const int b    = bn >> 4;
    const int t    = threadIdx.x;
    const int w    = t >> 5;
    const int lane = t & 31;

    // part[] = running per-warp max strips; init once
    part[t] = -INFINITY;
    part[t + 256] = -INFINITY;

    // ---- q: normalize + fp16 hi/lo split into swizzled tiles (shared) ----
    #pragma unroll
    for (int half = 0; half < 2; half++) {
        float4 v[4];
        #pragma unroll
        for (int i = 0; i < 4; i++)
            v[i] = *(const float4*)(qreps + ((size_t)(b * LQ + w + 8 * (half * 4 + i))) * DD + lane * 4);
        #pragma unroll
        for (int i = 0; i < 4; i++) {
            int qrow = w + 8 * (half * 4 + i);
            float ss = v[i].x * v[i].x + v[i].y * v[i].y + v[i].z * v[i].z + v[i].w * v[i].w;
            #pragma unroll
            for (int o = 16; o; o >>= 1) ss += __shfl_xor_sync(0xFFFFFFFFu, ss, o);
            float rnq = rsqrtf(fmaxf(ss, 1e-24f));
            float4 x = make_float4(v[i].x * rnq, v[i].y * rnq, v[i].z * rnq, v[i].w * rnq);
            u64 hi, lo; split4h(x, hi, lo);
            uint32_t byte = qrow * 256 + ((((lane >> 1) ^ (qrow & 7)) & 15) << 4) + ((lane & 1) << 3);
            *(u64*)(smem + S_QHI + byte) = hi;
            *(u64*)(smem + S_QLO + byte) = lo;
        }
    }
    __syncthreads();   // Q tiles + part init visible; the ONLY barrier before the end

    const float* dbase = dreps + (size_t)bn * LD * DD;
    const int*   mbase = dmask + bn * LD;

    // lane constants for ldmatrix addressing
    const int a_row   = w * 16 + (lane & 15);                // warp-exclusive rows
    const int a_cbadd = lane >> 4;
    const int b_rowp  = ((lane >> 4) & 1) * 8 + (lane & 7);
    const int b_cbadd = (lane >> 3) & 1;

    for (int c = 0; c < 2; c++) {
        // ---- warp-private: load 16 toks, normalize (+mask zero), cvt fp16 ----
        int mymk = (lane < 16) ? mbase[c * 128 + w * 16 + lane] : 0;
        unsigned mbits = __ballot_sync(0xFFFFFFFFu, mymk != 0) & 0xFFFFu;

        #pragma unroll
        for (int batch = 0; batch < 4; batch++) {
            float4 v[4];
            #pragma unroll
            for (int j = 0; j < 4; j++) {
                int tok = w * 16 + batch * 4 + j;
                v[j] = *(const float4*)(dbase + ((size_t)(c * 128 + tok)) * DD + lane * 4);
            }
            #pragma unroll
            for (int j = 0; j < 4; j++) {
                int tok = w * 16 + batch * 4 + j;
                float ss = v[j].x * v[j].x + v[j].y * v[j].y + v[j].z * v[j].z + v[j].w * v[j].w;
                #pragma unroll
                for (int o = 16; o; o >>= 1) ss += __shfl_xor_sync(0xFFFFFFFFu, ss, o);
                float sc = ((mbits >> (batch * 4 + j)) & 1) ? rsqrtf(fmaxf(ss, 1e-24f)) : 0.0f;
                float4 x = make_float4(v[j].x * sc, v[j].y * sc, v[j].z * sc, v[j].w * sc);
                u64 hv = cvt4h(x);
                uint32_t byte = tok * 256 + ((((lane >> 1) ^ (tok & 7)) & 15) << 4) + ((lane & 1) << 3);
                *(u64*)(smem + S_DH + byte) = hv;
            }
        }
        __syncwarp();   // warp-exclusive tile strip: warp-level sync suffices

        // ---- mainloop: 8 k-steps, 2-term fp16 (d single, q hi+lo), 8 n-tiles ----
        float acc[8][4];
        #pragma unroll
        for (int nt = 0; nt < 8; nt++)
            #pragma unroll
            for (int j = 0; j < 4; j++) acc[nt][j] = 0.0f;

        #pragma unroll
        for (int ks = 0; ks < 8; ks++) {
            uint32_t ah[4];
            {
                int cb = ((2 * ks + a_cbadd) ^ (a_row & 7)) & 15;
                ldsm4(ah, sbase + S_DH + a_row * 256 + (cb << 4));
            }
            #pragma unroll
            for (int p = 0; p < 4; p++) {
                int qrow = p * 16 + b_rowp;
                int cb = ((2 * ks + b_cbadd) ^ (qrow & 7)) & 15;
                uint32_t addr = qrow * 256 + (cb << 4);
                uint32_t bhi[4], blo[4];
                ldsm4(bhi, sbase + S_QHI + addr);
                ldsm4(blo, sbase + S_QLO + addr);
                mma_f16(acc[2 * p],     ah, bhi[0], bhi[1]);
                mma_f16(acc[2 * p],     ah, blo[0], blo[1]);
                mma_f16(acc[2 * p + 1], ah, bhi[2], bhi[3]);
                mma_f16(acc[2 * p + 1], ah, blo[2], blo[3]);
            }
        }
        __syncwarp();   // all LDSM reads done before next chunk overwrites strip

        // ---- epilogue: mask -> NEG, shfl-max over rows, fold into part[] ----
        {
            int rl = lane >> 2;
            bool on0 = (mbits >> rl) & 1;
            bool on1 = (mbits >> (rl + 8)) & 1;
            #pragma unroll
            for (int nt = 0; nt < 8; nt++) {
                float v0 = fmaxf(on0 ? acc[nt][0] : NEGV, on1 ? acc[nt][2] : NEGV);
                float v1 = fmaxf(on0 ? acc[nt][1] : NEGV, on1 ? acc[nt][3] : NEGV);
                #pragma unroll
                for (int o = 16; o >= 4; o >>= 1) {
                    v0 = fmaxf(v0, __shfl_xor_sync(0xFFFFFFFFu, v0, o));
                    v1 = fmaxf(v1, __shfl_xor_sync(0xFFFFFFFFu, v1, o));
                }
                if (lane < 4) {
                    float* s0 = &part[w * 64 + nt * 8 + lane * 2];
                    s0[0] = fmaxf(s0[0], v0);
                    s0[1] = fmaxf(s0[1], v1);
                }
            }
        }
        __syncwarp();
    }
    __syncthreads();

    // ---- cross-warp max over toks, then sum over q ----
    if (t < 64) {
        float v = part[t];
        #pragma unroll
        for (int w2 = 1; w2 < 8; w2++) v = fmaxf(v, part[w2 * 64 + t]);
        #pragma unroll
        for (int o = 16; o; o >>= 1) v += __shfl_xor_sync(0xFFFFFFFFu, v, o);
        if (lane == 0) ws[t >> 5] = v;
    }
    __syncthreads();

    __shared__ int is_last;
    if (t == 0) {
        g_scores[bn] = ws[0] + ws[1];
        __threadfence();
        is_last = (atomicAdd(&g_cnt, 1) == (BB * NWAY - 1)) ? 1 : 0;
    }
    __syncthreads();

    // ---- last CTA: softmax over nway + KL (batchmean, log_target) ----
    if (is_last) {
        __threadfence();
        if (t < 32) {
            int bb = t;
            float s[NWAY];
            float mx = -INFINITY;
            #pragma unroll
            for (int n = 0; n < NWAY; n++) {
                s[n] = g_scores[bb * NWAY + n];
                mx = fmaxf(mx, s[n]);
            }
            float se = 0.0f;
            #pragma unroll
            for (int n = 0; n < NWAY; n++) se += expf(s[n] - mx);
            float lse = mx + logf(se);
            float loss = 0.0f;
            #pragma unroll
            for (int n = 0; n < NWAY; n++) {
                float lab = labels[bb * NWAY + n];
                loss += expf(lab) * (lab - (s[n] - lse));
            }
            #pragma unroll
            for (int o = 16; o; o >>= 1) loss += __shfl_xor_sync(0xFFFFFFFFu, loss, o);
            if (t == 0) {
                out[0] = loss / (float)BB;
                g_cnt = 0;    // reset for next graph replay
            }
        }
    }
}

// ---------------------------------------------------------------------------
extern "C" void kernel_launch(void* const* d_in, const int* in_sizes, int n_in,
                              void* d_out, int out_size) {
    (void)in_sizes; (void)n_in; (void)out_size;
    const float* q      = (const float*)d_in[0];
    const float* dreps  = (const float*)d_in[1];
    const int*   dmask  = (const int*)  d_in[2];
    const float* labels = (const float*)d_in[3];

    cudaFuncSetAttribute(colbert_mma, cudaFuncAttributeMaxDynamicSharedMemorySize, S_TOTAL);
    colbert_mma<<<BB * NWAY, 256, S_TOTAL>>>(q, dreps, dmask, labels, (float*)d_out);
}

// round 12
// speedup vs baseline: 1.2200x; 1.2200x over previous
#include <cuda_runtime.h>
#include <cuda_fp16.h>
#include <math.h>
#include <stdint.h>

#define BB   32
#define NWAY 16
#define LQ   64
#define LD   256
#define DD   128
#define NEGV (-9999.0f)

typedef unsigned long long u64;

__device__ float g_scores[BB * NWAY];
__device__ int   g_cnt;                 // zero-init; reset by last CTA each launch

// ---------------- smem layout (dynamic) ----------------
// Tiles: 256B rows (16 x 16B units), unit swizzle: u' = u ^ (row & 7)
#define S_PART  0                       // 8*64 floats = 2048
#define S_WS    2048                    // 2 floats
#define S_QH    4096                    // 64 x 256B  = 16384
#define S_DH    20480                   // 128 x 256B = 32768 (warp-exclusive strips)
#define S_TOTAL 53248

__device__ __forceinline__ uint32_t smem_u32(const void* p) {
    uint32_t a;
    asm("{ .reg .u64 t; cvta.to.shared.u64 t, %1; cvt.u32.u64 %0, t; }" : "=r"(a) : "l"(p));
    return a;
}

__device__ __forceinline__ void ldsm4(uint32_t* r, uint32_t addr) {
    asm volatile("ldmatrix.sync.aligned.m8n8.x4.shared.b16 {%0,%1,%2,%3}, [%4];"
                 : "=r"(r[0]), "=r"(r[1]), "=r"(r[2]), "=r"(r[3]) : "r"(addr));
}

__device__ __forceinline__ void mma_f16(float* c, const uint32_t* a, uint32_t b0, uint32_t b1) {
    asm volatile(
        "mma.sync.aligned.m16n8k16.row.col.f32.f16.f16.f32 "
        "{%0,%1,%2,%3}, {%4,%5,%6,%7}, {%8,%9}, {%0,%1,%2,%3};"
        : "+f"(c[0]), "+f"(c[1]), "+f"(c[2]), "+f"(c[3])
        : "r"(a[0]), "r"(a[1]), "r"(a[2]), "r"(a[3]), "r"(b0), "r"(b1));
}

// float4 -> 4 fp16 (rounded), packed in u64
__device__ __forceinline__ u64 cvt4h(float4 v) {
    __half2 a = __floats2half2_rn(v.x, v.y);
    __half2 b = __floats2half2_rn(v.z, v.w);
    return (u64)*(uint32_t*)&a | ((u64)*(uint32_t*)&b << 32);
}

// ---------------------------------------------------------------------------
// One CTA per (b,n). 256 threads, 2 CTAs/SM.
// ---------------------------------------------------------------------------
__global__ void __launch_bounds__(256, 2) colbert_mma(
    const float* __restrict__ qreps, const float* __restrict__ dreps,
    const int* __restrict__ dmask, const float* __restrict__ labels,
    float* __restrict__ out)
{
    extern __shared__ char smem[];
    const uint32_t sbase = smem_u32(smem);
    float* part = (float*)(smem + S_PART);
    float* ws   = (float*)(smem + S_WS);

    const int bn   = blockIdx.x;       // b*16 + n
    const int b    = bn >> 4;
    const int t    = threadIdx.x;
    const int w    = t >> 5;
    const int lane = t & 31;

    // ---- q: normalize + fp16 cvt into swizzled tile (shared) ----
    {
        float4 v[8];
        #pragma unroll
        for (int i = 0; i < 8; i++)
            v[i] = *(const float4*)(qreps + ((size_t)(b * LQ + w + 8 * i)) * DD + lane * 4);
        #pragma unroll
        for (int i = 0; i < 8; i++) {
            int qrow = w + 8 * i;
            float ss = v[i].x * v[i].x + v[i].y * v[i].y + v[i].z * v[i].z + v[i].w * v[i].w;
            #pragma unroll
            for (int o = 16; o; o >>= 1) ss += __shfl_xor_sync(0xFFFFFFFFu, ss, o);
            float rnq = rsqrtf(fmaxf(ss, 1e-24f));
            float4 x = make_float4(v[i].x * rnq, v[i].y * rnq, v[i].z * rnq, v[i].w * rnq);
            u64 hv = cvt4h(x);
            uint32_t byte = qrow * 256 + ((((lane >> 1) ^ (qrow & 7)) & 15) << 4) + ((lane & 1) << 3);
            *(u64*)(smem + S_QH + byte) = hv;
        }
    }
    __syncthreads();   // Q tile visible to all warps; the ONLY barrier before the end

    const float* dbase = dreps + (size_t)bn * LD * DD;
    const int*   mbase = dmask + bn * LD;

    // lane constants for ldmatrix addressing
    const int a_row   = w * 16 + (lane & 15);                // warp-exclusive rows
    const int a_cbadd = lane >> 4;
    const int b_rowp  = ((lane >> 4) & 1) * 8 + (lane & 7);
    const int b_cbadd = (lane >> 3) & 1;

    float m[16];
    #pragma unroll
    for (int i = 0; i < 16; i++) m[i] = -INFINITY;

    for (int c = 0; c < 2; c++) {
        // ---- warp-private: load 16 toks, normalize (+mask zero), cvt fp16 ----
        int mymk = (lane < 16) ? mbase[c * 128 + w * 16 + lane] : 0;
        unsigned mbits = __ballot_sync(0xFFFFFFFFu, mymk != 0) & 0xFFFFu;

        #pragma unroll
        for (int batch = 0; batch < 2; batch++) {
            float4 v[8];
            #pragma unroll
            for (int j = 0; j < 8; j++) {
                int tok = w * 16 + batch * 8 + j;
                v[j] = *(const float4*)(dbase + ((size_t)(c * 128 + tok)) * DD + lane * 4);
            }
            #pragma unroll
            for (int j = 0; j < 8; j++) {
                int tok = w * 16 + batch * 8 + j;
                float ss = v[j].x * v[j].x + v[j].y * v[j].y + v[j].z * v[j].z + v[j].w * v[j].w;
                #pragma unroll
                for (int o = 16; o; o >>= 1) ss += __shfl_xor_sync(0xFFFFFFFFu, ss, o);
                float sc = ((mbits >> (batch * 8 + j)) & 1) ? rsqrtf(fmaxf(ss, 1e-24f)) : 0.0f;
                float4 x = make_float4(v[j].x * sc, v[j].y * sc, v[j].z * sc, v[j].w * sc);
                u64 hv = cvt4h(x);
                uint32_t byte = tok * 256 + ((((lane >> 1) ^ (tok & 7)) & 15) << 4) + ((lane & 1) << 3);
                *(u64*)(smem + S_DH + byte) = hv;
            }
        }
        __syncwarp();   // warp-exclusive tile strip: warp-level sync suffices

        // ---- mainloop: 8 k-steps, single fp16 term, 8 n-tiles ----
        float acc[8][4];
        #pragma unroll
        for (int nt = 0; nt < 8; nt++)
            #pragma unroll
            for (int j = 0; j < 4; j++) acc[nt][j] = 0.0f;

        #pragma unroll
        for (int ks = 0; ks < 8; ks++) {
            uint32_t ah[4];
            {
                int cb = ((2 * ks + a_cbadd) ^ (a_row & 7)) & 15;
                ldsm4(ah, sbase + S_DH + a_row * 256 + (cb << 4));
            }
            #pragma unroll
            for (int p = 0; p < 4; p++) {
                int qrow = p * 16 + b_rowp;
                int cb = ((2 * ks + b_cbadd) ^ (qrow & 7)) & 15;
                uint32_t bh[4];
                ldsm4(bh, sbase + S_QH + qrow * 256 + (cb << 4));
                mma_f16(acc[2 * p],     ah, bh[0], bh[1]);
                mma_f16(acc[2 * p + 1], ah, bh[2], bh[3]);
            }
        }
        __syncwarp();   // all LDSM reads done before next chunk overwrites strip

        // ---- epilogue: mask -> NEG, fold rows into per-lane q-col max ----
        {
            int rl = lane >> 2;
            bool on0 = (mbits >> rl) & 1;
            bool on1 = (mbits >> (rl + 8)) & 1;
            #pragma unroll
            for (int nt = 0; nt < 8; nt++) {
                float v0 = fmaxf(on0 ? acc[nt][0] : NEGV, on1 ? acc[nt][2] : NEGV);
                float v1 = fmaxf(on0 ? acc[nt][1] : NEGV, on1 ? acc[nt][3] : NEGV);
                m[2 * nt]     = fmaxf(m[2 * nt],     v0);
                m[2 * nt + 1] = fmaxf(m[2 * nt + 1], v1);
            }
        }
    }

    // ---- lane reduce: max over lanes sharing the same q column ----
    #pragma unroll
    for (int i = 0; i < 16; i++) {
        float v = m[i];
        v = fmaxf(v, __shfl_xor_sync(0xFFFFFFFFu, v, 4));
        v = fmaxf(v, __shfl_xor_sync(0xFFFFFFFFu, v, 8));
        v = fmaxf(v, __shfl_xor_sync(0xFFFFFFFFu, v, 16));
        m[i] = v;
    }
    if (lane < 4) {
        #pragma unroll
        for (int nt = 0; nt < 8; nt++) {
            part[w * 64 + nt * 8 + lane * 2 + 0] = m[2 * nt];
            part[w * 64 + nt * 8 + lane * 2 + 1] = m[2 * nt + 1];
        }
    }
    __syncthreads();

    // ---- cross-warp max over toks, then sum over q ----
    if (t < 64) {
        float v = part[t];
        #pragma unroll
        for (int w2 = 1; w2 < 8; w2++) v = fmaxf(v, part[w2 * 64 + t]);
        #pragma unroll
        for (int o = 16; o; o >>= 1) v += __shfl_xor_sync(0xFFFFFFFFu, v, o);
        if (lane == 0) ws[t >> 5] = v;
    }
    __syncthreads();

    __shared__ int is_last;
    if (t == 0) {
        g_scores[bn] = ws[0] + ws[1];
        __threadfence();
        is_last = (atomicAdd(&g_cnt, 1) == (BB * NWAY - 1)) ? 1 : 0;
    }
    __syncthreads();

    // ---- last CTA: softmax over nway + KL (batchmean, log_target) ----
    if (is_last) {
        __threadfence();
        if (t < 32) {
            int bb = t;
            float s[NWAY];
            float mx = -INFINITY;
            #pragma unroll
            for (int n = 0; n < NWAY; n++) {
                s[n] = g_scores[bb * NWAY + n];
                mx = fmaxf(mx, s[n]);
            }
            float se = 0.0f;
            #pragma unroll
            for (int n = 0; n < NWAY; n++) se += expf(s[n] - mx);
            float lse = mx + logf(se);
            float loss = 0.0f;
            #pragma unroll
            for (int n = 0; n < NWAY; n++) {
                float lab = labels[bb * NWAY + n];
                loss += expf(lab) * (lab - (s[n] - lse));
            }
            #pragma unroll
            for (int o = 16; o; o >>= 1) loss += __shfl_xor_sync(0xFFFFFFFFu, loss, o);
            if (t == 0) {
                out[0] = loss / (float)BB;
                g_cnt = 0;    // reset for next graph replay
            }
        }
    }
}

// ---------------------------------------------------------------------------
extern "C" void kernel_launch(void* const* d_in, const int* in_sizes, int n_in,
                              void* d_out, int out_size) {
    (void)in_sizes; (void)n_in; (void)out_size;
    const float* q      = (const float*)d_in[0];
    const float* dreps  = (const float*)d_in[1];
    const int*   dmask  = (const int*)  d_in[2];
    const float* labels = (const float*)d_in[3];

    cudaFuncSetAttribute(colbert_mma, cudaFuncAttributeMaxDynamicSharedMemorySize, S_TOTAL);
    colbert_mma<<<BB * NWAY, 256, S_TOTAL>>>(q, dreps, dmask, labels, (float*)d_out);
}